// round 12
// baseline (speedup 1.0000x reference)
#include <cuda_runtime.h>
#include <math.h>
#include <stdint.h>

#define L   401
#define B   256
#define LL  (L * L)
#define NCHUNK 4                 // batch chunks in main grid
#define BCHUNK (B / NCHUNK)      // 64 batches per main block (2 bit-plane words)
#define PW  (3 * L)              // words per batch-word slab: [plane][j]
#define NBLK (NCHUNK * L)        // 1604 main blocks
#define NT  512                  // threads per main block

// ---------------- device globals ----------------
__device__ float    g_bins[L * 32];        // one bin per 128B line: bin d at [d*32]
__device__ float    g_scf[2 * 32];         // [0]=ctcf_num, [32]=within_num
__device__ int      g_sci[2 * 32];         // [0]=nc_sum,   [32]=cnt_within (exact ints)
__device__ uint32_t g_planes[8 * PW];      // [batch_word][plane f/r/c][j], bit = b%32
__device__ unsigned int g_done;

// ---------------- kernel 1: merged prep (planes + analytic counts) ----------------
__global__ __launch_bounds__(512) void prep_kernel(const int* __restrict__ ctcf,
                                                   const float* __restrict__ logits) {
    const int blk = blockIdx.x;
    const int t   = threadIdx.x;

    if (blk < L) {
        if (t < B) {
            const int p = blk, b = t;
            int o = ctcf[b * L + p];
            float l0 = logits[(b * L + p) * 2 + 0];
            float l1 = logits[(b * L + p) * 2 + 1];
            uint32_t bf = __ballot_sync(0xffffffffu, o == 1);
            uint32_t br = __ballot_sync(0xffffffffu, o == -1);
            uint32_t bc = __ballot_sync(0xffffffffu, l1 > l0);
            if ((b & 31) == 0) {
                int w = b >> 5;
                g_planes[w * PW + 0 * L + p] = bf;
                g_planes[w * PW + 1 * L + p] = br;
                g_planes[w * PW + 2 * L + p] = bc;
            }
        }
    } else {
        const int b = blk - L;
        const int p = t;
        __shared__ int cnt[5];                 // A, F, R, n1, adjEq
        __shared__ unsigned char compsh[L];
        if (p < 5) cnt[p] = 0;
        __syncthreads();

        int a = 0, f = 0, r = 0, c = 0;
        if (p < L) {
            int o = ctcf[b * L + p];
            a = (o != 0);
            f = (o == 1);
            r = (o == -1);
            float l0 = logits[(b * L + p) * 2 + 0];
            float l1 = logits[(b * L + p) * 2 + 1];
            c = (l1 > l0);                     // argmax, ties -> 0
            compsh[p] = (unsigned char)c;
        }
        __syncthreads();

        int adj = 0;
        if (p < L - 1) adj = (compsh[p] == compsh[p + 1]);

        atomicAdd(&cnt[0], a);
        atomicAdd(&cnt[1], f);
        atomicAdd(&cnt[2], r);
        atomicAdd(&cnt[3], c);
        atomicAdd(&cnt[4], adj);
        __syncthreads();

        if (p == 0) {
            int A = cnt[0], F = cnt[1], R = cnt[2], n1 = cnt[3];
            int n0 = L - n1;
            int nc = A * A - F * R;                            // non_conv count (exact)
            int cw = n0 * n0 + n1 * n1 - L - 2 * cnt[4];       // same & d>=2 (exact)
            atomicAdd(&g_sci[0],  nc);
            atomicAdd(&g_sci[32], cw);
        }
    }
}

// ---------------- kernel 2: float4 streaming pass + last-block finalize ----------
// block = (batch chunk c, row i). Batch-residue classes: class r = b%4 has
// constant row-start alignment pre_r, so threads own FIXED 16B-aligned float4
// columns and accumulate 4 bins in registers. r = tid>>7, g = tid&127.
__global__ __launch_bounds__(NT) void main_kernel(const float* __restrict__ cm,
                                                  float* __restrict__ out) {
    const int i   = blockIdx.y;
    const int tid = threadIdx.x;
    const int c   = blockIdx.x;
    const int b0  = c * BCHUNK;            // b0 % 4 == 0
    const int w0  = c * 2;                 // first batch-word of this chunk

    __shared__ uint32_t shp[2 * PW];       // 9.6 KB plane slab
    for (int idx = tid; idx < 2 * PW; idx += NT)
        shp[idx] = g_planes[w0 * PW + idx];
    __syncthreads();

    float ct = 0.f, wn = 0.f;

    const int r  = tid >> 7;               // class 0..3 (warp-uniform)
    const int g  = tid & 127;              // float4 group
    const int pre = (4 - ((r + i) & 3)) & 3;
    const int G   = (401 - pre) >> 2;      // 99 or 100 groups

    // hoisted i-side plane words
    const uint32_t fi0 = shp[i],          ri0 = shp[L + i],          ci0 = shp[2 * L + i];
    const uint32_t fi1 = shp[PW + i],     ri1 = shp[PW + L + i],     ci1 = shp[PW + 2 * L + i];
    const uint32_t ai0 = fi0 | ri0,       ai1 = fi1 | ri1;

    if (g < G) {
        const int jb = pre + 4 * g;        // first of 4 owned columns

        // condensed 16-bit masks per column: bit s (batch b0+r+4s) for m10;
        // bit s+16 for m20.
        uint32_t mm[4];
#pragma unroll
        for (int k = 0; k < 4; ++k) {
            const int j = jb + k;
            const int d = abs(i - j);
            uint32_t M10[2], M20[2];
            {
                uint32_t fj = shp[j], rj = shp[L + j], cj = shp[2 * L + j];
                M10[0] = ai0 & (fj | rj) & ~(fi0 & rj);
                M20[0] = (d >= 2) ? ~(ci0 ^ cj) : 0u;
                fj = shp[PW + j]; rj = shp[PW + L + j]; cj = shp[PW + 2 * L + j];
                M10[1] = ai1 & (fj | rj) & ~(fi1 & rj);
                M20[1] = (d >= 2) ? ~(ci1 ^ cj) : 0u;
            }
            uint32_t m = 0;
#pragma unroll
            for (int s = 0; s < 16; ++s) {
                const int h = s >> 3;
                const int bit = r + 4 * (s & 7);
                m |= ((M10[h] >> bit) & 1u) << s;
                m |= ((M20[h] >> bit) & 1u) << (s + 16);
            }
            mm[k] = m;
        }

        float acc[4] = {0.f, 0.f, 0.f, 0.f};
        const float4* p4 = reinterpret_cast<const float4*>(
            cm + (size_t)(b0 + r) * LL + (size_t)i * L + jb);

#pragma unroll
        for (int s = 0; s < 16; ++s) {
            float4 v = __ldg(p4 + (size_t)s * LL);   // batch step 4*LL floats = LL float4
            acc[0] += v.x;
            acc[1] += v.y;
            acc[2] += v.z;
            acc[3] += v.w;
            if ((mm[0] >> s) & 1u) ct += fmaxf(v.x, 0.f);
            if ((mm[1] >> s) & 1u) ct += fmaxf(v.y, 0.f);
            if ((mm[2] >> s) & 1u) ct += fmaxf(v.z, 0.f);
            if ((mm[3] >> s) & 1u) ct += fmaxf(v.w, 0.f);
            if ((mm[0] >> (s + 16)) & 1u) wn += v.x;
            if ((mm[1] >> (s + 16)) & 1u) wn += v.y;
            if ((mm[2] >> (s + 16)) & 1u) wn += v.z;
            if ((mm[3] >> (s + 16)) & 1u) wn += v.w;
        }

#pragma unroll
        for (int k = 0; k < 4; ++k)
            atomicAdd(&g_bins[abs(i - (jb + k)) * 32], acc[k]);
    } else if (tid >= 496) {
        // leftover j-slots not covered by any class's aligned float4s:
        // per class r2: head [0, pre_r2) + tail [pre_r2+4G_r2, 401). Total = 12.
        int idx = tid - 496;
        int r2 = -1, j = -1;
        for (int rr = 0; rr < 4 && r2 < 0; ++rr) {
            const int p2 = (4 - ((rr + i) & 3)) & 3;
            const int G2 = (401 - p2) >> 2;
            const int nlo = p2;
            const int nhi = 401 - p2 - 4 * G2;
            if (idx < nlo + nhi) {
                r2 = rr;
                j = (idx < nlo) ? idx : (p2 + 4 * G2 + (idx - nlo));
            } else idx -= nlo + nhi;
        }
        if (r2 >= 0) {
            const int d = abs(i - j);
            uint32_t M10[2], M20[2];
            {
                uint32_t fj = shp[j], rj = shp[L + j], cj = shp[2 * L + j];
                M10[0] = ai0 & (fj | rj) & ~(fi0 & rj);
                M20[0] = (d >= 2) ? ~(ci0 ^ cj) : 0u;
                fj = shp[PW + j]; rj = shp[PW + L + j]; cj = shp[PW + 2 * L + j];
                M10[1] = ai1 & (fj | rj) & ~(fi1 & rj);
                M20[1] = (d >= 2) ? ~(ci1 ^ cj) : 0u;
            }
            float acc = 0.f;
            const float* p = cm + (size_t)(b0 + r2) * LL + (size_t)i * L + j;
#pragma unroll
            for (int s = 0; s < 16; ++s) {
                float v = __ldg(p + (size_t)s * 4 * LL);
                acc += v;
                const int h = s >> 3;
                const int bit = r2 + 4 * (s & 7);
                if ((M10[h] >> bit) & 1u) ct += fmaxf(v, 0.f);
                if ((M20[h] >> bit) & 1u) wn += v;
            }
            atomicAdd(&g_bins[d * 32], acc);
        }
    }

    // block-reduce scalars -> one float atomic each
    for (int o = 16; o; o >>= 1) {
        ct += __shfl_down_sync(0xffffffffu, ct, o);
        wn += __shfl_down_sync(0xffffffffu, wn, o);
    }
    __shared__ float red[2][16];
    const int wid = tid >> 5, lane = tid & 31;
    if (lane == 0) { red[0][wid] = ct; red[1][wid] = wn; }
    __syncthreads();
    if (tid == 0) {
        float cs = 0.f, ws = 0.f;
#pragma unroll
        for (int k = 0; k < 16; ++k) { cs += red[0][k]; ws += red[1][k]; }
        atomicAdd(&g_scf[0],  cs);
        atomicAdd(&g_scf[32], ws);
    }

    // ---------- last-block finalize ----------
    __threadfence();
    __shared__ unsigned int rank_sh;
    if (tid == 0) rank_sh = atomicAdd(&g_done, 1u);
    __syncthreads();
    if (rank_sh != NBLK - 1) return;
    __threadfence();

    float w0_ = 0.f, ld0 = 0.f, lp0 = 0.f;
    float v4a[4] = {0.f, 0.f, 0.f, 0.f};    // n, sum(w*ld), sum(w*lp), masked-sum
    if (tid < L) {
        float binv = g_bins[tid * 32];
        float cntp = (tid == 0) ? (float)L : 2.0f * (float)(L - tid);
        float mc = binv / (cntp * (float)B);
        bool valid = (tid >= 2) && isfinite(mc) && (mc > 0.0f);
        w0_ = valid ? 1.f : 0.f;
        ld0 = logf(fmaxf((float)tid, 1.0f));
        lp0 = logf((valid ? mc : 1.0f) + 1e-6f);
        v4a[0] = w0_; v4a[1] = w0_ * ld0; v4a[2] = w0_ * lp0;
        if (tid >= 2) v4a[3] = binv;
    }

    __shared__ float sc4[4][16];
    __shared__ float tot[4];
#pragma unroll
    for (int o = 16; o; o >>= 1)
#pragma unroll
        for (int q = 0; q < 4; ++q) v4a[q] += __shfl_down_sync(0xffffffffu, v4a[q], o);
    if (lane == 0) { sc4[0][wid] = v4a[0]; sc4[1][wid] = v4a[1]; sc4[2][wid] = v4a[2]; sc4[3][wid] = v4a[3]; }
    __syncthreads();
    if (tid < 4) {
        float sAcc = 0.f;
#pragma unroll
        for (int k = 0; k < 16; ++k) sAcc += sc4[tid][k];
        tot[tid] = sAcc;
    }
    __syncthreads();

    const float n  = tot[0];
    const float ns = fmaxf(n, 1.0f);
    const float xm = tot[1] / ns, ym = tot[2] / ns;
    const float msk = tot[3];

    float v2[2];
    v2[0] = w0_ * (ld0 - xm) * (lp0 - ym);
    v2[1] = w0_ * (ld0 - xm) * (ld0 - xm);
#pragma unroll
    for (int o = 16; o; o >>= 1)
#pragma unroll
        for (int q = 0; q < 2; ++q) v2[q] += __shfl_down_sync(0xffffffffu, v2[q], o);
    if (lane == 0) { sc4[0][wid] = v2[0]; sc4[1][wid] = v2[1]; }
    __syncthreads();
    if (tid == 0) {
        float num = 0.f, den = 0.f;
#pragma unroll
        for (int k = 0; k < 16; ++k) { num += sc4[0][k]; den += sc4[1][k]; }

        // distance decay
        double slope = (double)num / ((double)den + 1e-8);
        double dist  = (n >= 5.0f) ? (slope + 0.85) * (slope + 0.85) : 0.0;
        // ctcf
        double ncs   = (double)g_sci[0];
        double hinge = (double)g_scf[0] / (ncs + 1e-6);
        double ctcfl = (ncs < 1.0) ? 0.0 : hinge;
        // compartment
        double cw      = (double)g_sci[32];
        double cb      = 159600.0 * (double)B - cw;   // (L-1)(L-2) masked pairs per batch
        double within  = (double)g_scf[32] / fmax(cw, 1.0);
        double between = ((double)msk - (double)g_scf[32]) / fmax(cb, 1.0);
        double ratio   = within / (fabs(between) + 1e-6);
        double compl_  = fmax(1.5 - ratio, 0.0);

        out[0] = (float)dist;
        out[1] = (float)ctcfl;
        out[2] = (float)compl_;
        out[3] = (float)(dist + 0.5 * ctcfl + 0.5 * compl_);
    }

    // ---------- reset state for next replay ----------
    __syncthreads();
    if (tid < L) g_bins[tid * 32] = 0.f;
    if (tid < 2) { g_scf[tid * 32] = 0.f; g_sci[tid * 32] = 0; }
    if (tid == 0) g_done = 0u;
}

// ---------------- launch ----------------
extern "C" void kernel_launch(void* const* d_in, const int* in_sizes, int n_in,
                              void* d_out, int out_size) {
    const float* cm     = (const float*)d_in[0];   // (B, L, L) f32
    const float* logits = (const float*)d_in[1];   // (B, L, 2) f32
    const int*   ctcf   = (const int*)d_in[2];     // (B, L)    i32
    float*       out    = (float*)d_out;           // 4 f32

    prep_kernel<<<L + B, 512>>>(ctcf, logits);
    dim3 grid(NCHUNK, L);
    main_kernel<<<grid, NT>>>(cm, out);
}

// round 14
// speedup vs baseline: 1.9500x; 1.9500x over previous
#include <cuda_runtime.h>
#include <math.h>
#include <stdint.h>

#define L   401
#define B   256
#define LL  (L * L)
#define NCHUNK 4                 // batch chunks in main grid
#define BCHUNK (B / NCHUNK)      // 64 batches per main block (2 bit-plane words)
#define PW  (3 * L)              // words per batch-word slab: [plane][j]
#define NBLK (NCHUNK * L)        // 1604 main blocks

// ---------------- device globals ----------------
__device__ float    g_bins[L * 32];        // one bin per 128B line: bin d at [d*32]
__device__ float    g_scf[2 * 32];         // [0]=ctcf_num, [32]=within_num
__device__ int      g_sci[2 * 32];         // [0]=nc_sum,   [32]=cnt_within (exact ints)
__device__ uint32_t g_planes[8 * PW];      // [batch_word][plane f/r/c][j], bit = b%32
__device__ unsigned int g_done;

// ---------------- kernel 1: merged prep (planes + analytic counts) ----------------
__global__ __launch_bounds__(512) void prep_kernel(const int* __restrict__ ctcf,
                                                   const float* __restrict__ logits) {
    const int blk = blockIdx.x;
    const int t   = threadIdx.x;

    if (blk < L) {
        if (t < B) {
            const int p = blk, b = t;
            int o = ctcf[b * L + p];
            float l0 = logits[(b * L + p) * 2 + 0];
            float l1 = logits[(b * L + p) * 2 + 1];
            uint32_t bf = __ballot_sync(0xffffffffu, o == 1);
            uint32_t br = __ballot_sync(0xffffffffu, o == -1);
            uint32_t bc = __ballot_sync(0xffffffffu, l1 > l0);
            if ((b & 31) == 0) {
                int w = b >> 5;
                g_planes[w * PW + 0 * L + p] = bf;
                g_planes[w * PW + 1 * L + p] = br;
                g_planes[w * PW + 2 * L + p] = bc;
            }
        }
    } else {
        const int b = blk - L;
        const int p = t;
        __shared__ int cnt[5];                 // A, F, R, n1, adjEq
        __shared__ unsigned char compsh[L];
        if (p < 5) cnt[p] = 0;
        __syncthreads();

        int a = 0, f = 0, r = 0, c = 0;
        if (p < L) {
            int o = ctcf[b * L + p];
            a = (o != 0);
            f = (o == 1);
            r = (o == -1);
            float l0 = logits[(b * L + p) * 2 + 0];
            float l1 = logits[(b * L + p) * 2 + 1];
            c = (l1 > l0);                     // argmax, ties -> 0
            compsh[p] = (unsigned char)c;
        }
        __syncthreads();

        int adj = 0;
        if (p < L - 1) adj = (compsh[p] == compsh[p + 1]);

        atomicAdd(&cnt[0], a);
        atomicAdd(&cnt[1], f);
        atomicAdd(&cnt[2], r);
        atomicAdd(&cnt[3], c);
        atomicAdd(&cnt[4], adj);
        __syncthreads();

        if (p == 0) {
            int A = cnt[0], F = cnt[1], R = cnt[2], n1 = cnt[3];
            int n0 = L - n1;
            int nc = A * A - F * R;                            // non_conv count (exact)
            int cw = n0 * n0 + n1 * n1 - L - 2 * cnt[4];       // same & d>=2 (exact)
            atomicAdd(&g_sci[0],  nc);
            atomicAdd(&g_sci[32], cw);
        }
    }
}

// ---------------- kernel 2: L2-prefetched streaming pass + last-block finalize ----
// block = (batch chunk, row i); thread tid owns j0 = tid and (tid<145) j1 = tid+256.
// All of the block's lines are prefetched into L2 up front (fire-and-forget, no
// MSHR slots), so demand LDGs complete at L2-hit latency instead of DRAM latency.
__global__ __launch_bounds__(256) void main_kernel(const float* __restrict__ cm,
                                                   float* __restrict__ out) {
    const int i   = blockIdx.y;
    const int tid = threadIdx.x;
    const int w0  = blockIdx.x * 2;        // first batch-word of this chunk

    __shared__ uint32_t sh[2 * PW];        // 9.6 KB: the 2 batch-words this block needs

    // ---- cooperative L2 prefetch of this block's 64 row-slices ----
    {
        const char* cmb = (const char*)cm;
        const size_t total = (size_t)B * LL * 4u;
        const size_t row0 = ((size_t)(blockIdx.x * BCHUNK) * LL + (size_t)i * L) * 4u;
        // 64 rows x 14 lines (1604B spans <= 14 x 128B lines incl. misalignment)
        for (int idx = tid; idx < BCHUNK * 14; idx += 256) {
            const int bb = idx / 14;
            const int ln = idx % 14;
            size_t off = ((row0 + (size_t)bb * LL * 4u) & ~(size_t)127) + (size_t)ln * 128u;
            if (off < total)
                asm volatile("prefetch.global.L2 [%0];" :: "l"(cmb + off));
        }
    }

    for (int idx = tid; idx < 2 * PW; idx += 256)
        sh[idx] = g_planes[w0 * PW + idx];
    __syncthreads();

    const int  j0   = tid;
    const int  j1   = tid + 256;
    const bool has1 = (j1 < L);
    const int  d0   = abs(i - j0);
    const int  d1   = has1 ? abs(i - j1) : 0;

    float s0 = 0.f, s1 = 0.f, ct = 0.f, wn = 0.f;
    const float* base = cm + (size_t)(blockIdx.x * BCHUNK) * LL + (size_t)i * L + j0;

#pragma unroll
    for (int h = 0; h < 2; ++h) {
        const uint32_t* s = sh + h * PW;
        const uint32_t fi = s[i], ri = s[L + i], ci = s[2 * L + i];
        const uint32_t ai = fi | ri;

        const uint32_t fj = s[j0], rj = s[L + j0], cj = s[2 * L + j0];
        const uint32_t t10 = ai & (fj | rj) & ~(fi & rj);    // ctcf pair & not convergent
        const uint32_t t20 = (d0 >= 2) ? ~(ci ^ cj) : 0u;    // same compartment & d>=2

        uint32_t t11 = 0u, t21 = 0u;
        if (has1) {
            uint32_t fk = s[j1], rk = s[L + j1], ck = s[2 * L + j1];
            t11 = ai & (fk | rk) & ~(fi & rk);
            t21 = (d1 >= 2) ? ~(ci ^ ck) : 0u;
        }

        const float* pb = base + h * 32 * LL;

#pragma unroll
        for (int c4 = 0; c4 < 4; ++c4) {
            // batch-issue 8 (+8) loads before any consumption
            float v0[8], v1[8];
#pragma unroll
            for (int k = 0; k < 8; ++k)
                v0[k] = __ldcs(pb + (c4 * 8 + k) * LL);
            if (has1) {
#pragma unroll
                for (int k = 0; k < 8; ++k)
                    v1[k] = __ldcs(pb + (c4 * 8 + k) * LL + 256);
            }

#pragma unroll
            for (int k = 0; k < 8; ++k) {
                const int kk = c4 * 8 + k;
                float v = v0[k];
                s0 += v;
                if ((t10 >> kk) & 1u) ct += fmaxf(v, 0.f);
                if ((t20 >> kk) & 1u) wn += v;
            }
            if (has1) {
#pragma unroll
                for (int k = 0; k < 8; ++k) {
                    const int kk = c4 * 8 + k;
                    float u = v1[k];
                    s1 += u;
                    if ((t11 >> kk) & 1u) ct += fmaxf(u, 0.f);
                    if ((t21 >> kk) & 1u) wn += u;
                }
            }
        }
    }

    // one float atomic per thread-slot; bins padded to 1 per 128B line (401 LTS slices)
    atomicAdd(&g_bins[d0 * 32], s0);
    if (has1) atomicAdd(&g_bins[d1 * 32], s1);

    // block-reduce scalars -> one float atomic each
    for (int o = 16; o; o >>= 1) {
        ct += __shfl_down_sync(0xffffffffu, ct, o);
        wn += __shfl_down_sync(0xffffffffu, wn, o);
    }
    __shared__ float red[2][8];
    int wid = tid >> 5, lane = tid & 31;
    if (lane == 0) { red[0][wid] = ct; red[1][wid] = wn; }
    __syncthreads();
    if (tid == 0) {
        float c = 0.f, ww = 0.f;
#pragma unroll
        for (int k = 0; k < 8; ++k) { c += red[0][k]; ww += red[1][k]; }
        atomicAdd(&g_scf[0],  c);
        atomicAdd(&g_scf[32], ww);
    }

    // ---------- last-block finalize ----------
    __threadfence();
    __shared__ unsigned int rank_sh;
    if (tid == 0) rank_sh = atomicAdd(&g_done, 1u);
    __syncthreads();
    if (rank_sh != NBLK - 1) return;
    __threadfence();

    const int t0 = tid, t1 = tid + 256;
    const bool hb1 = (t1 < L);

    float w0_ = 0.f, ld0 = 0.f, lp0 = 0.f;
    float w1_ = 0.f, ld1 = 0.f, lp1 = 0.f;
    float v4[4] = {0.f, 0.f, 0.f, 0.f};    // n, sum(w*ld), sum(w*lp), masked-sum
    {
        float binv = g_bins[t0 * 32];
        float cntp = (t0 == 0) ? (float)L : 2.0f * (float)(L - t0);
        float mc = binv / (cntp * (float)B);
        bool valid = (t0 >= 2) && isfinite(mc) && (mc > 0.0f);
        w0_ = valid ? 1.f : 0.f;
        ld0 = logf(fmaxf((float)t0, 1.0f));
        lp0 = logf((valid ? mc : 1.0f) + 1e-6f);
        v4[0] += w0_; v4[1] += w0_ * ld0; v4[2] += w0_ * lp0;
        if (t0 >= 2) v4[3] += binv;
    }
    if (hb1) {
        float binv = g_bins[t1 * 32];
        float cntp = 2.0f * (float)(L - t1);
        float mc = binv / (cntp * (float)B);
        bool valid = isfinite(mc) && (mc > 0.0f);   // t1 >= 256 >= 2 always
        w1_ = valid ? 1.f : 0.f;
        ld1 = logf((float)t1);
        lp1 = logf((valid ? mc : 1.0f) + 1e-6f);
        v4[0] += w1_; v4[1] += w1_ * ld1; v4[2] += w1_ * lp1;
        v4[3] += binv;
    }

    __shared__ float sc4[4][8];
    __shared__ float tot[4];
#pragma unroll
    for (int o = 16; o; o >>= 1)
#pragma unroll
        for (int q = 0; q < 4; ++q) v4[q] += __shfl_down_sync(0xffffffffu, v4[q], o);
    if (lane == 0) { sc4[0][wid] = v4[0]; sc4[1][wid] = v4[1]; sc4[2][wid] = v4[2]; sc4[3][wid] = v4[3]; }
    __syncthreads();
    if (tid < 4) {
        float sAcc = 0.f;
#pragma unroll
        for (int k = 0; k < 8; ++k) sAcc += sc4[tid][k];
        tot[tid] = sAcc;
    }
    __syncthreads();

    float n  = tot[0];
    float ns = fmaxf(n, 1.0f);
    float xm = tot[1] / ns, ym = tot[2] / ns;
    float msk = tot[3];

    float v2[2];
    v2[0] = w0_ * (ld0 - xm) * (lp0 - ym) + w1_ * (ld1 - xm) * (lp1 - ym);
    v2[1] = w0_ * (ld0 - xm) * (ld0 - xm) + w1_ * (ld1 - xm) * (ld1 - xm);
#pragma unroll
    for (int o = 16; o; o >>= 1)
#pragma unroll
        for (int q = 0; q < 2; ++q) v2[q] += __shfl_down_sync(0xffffffffu, v2[q], o);
    if (lane == 0) { sc4[0][wid] = v2[0]; sc4[1][wid] = v2[1]; }
    __syncthreads();
    if (tid == 0) {
        float num = 0.f, den = 0.f;
#pragma unroll
        for (int k = 0; k < 8; ++k) { num += sc4[0][k]; den += sc4[1][k]; }

        // distance decay
        double slope = (double)num / ((double)den + 1e-8);
        double dist  = (n >= 5.0f) ? (slope + 0.85) * (slope + 0.85) : 0.0;
        // ctcf
        double ncs   = (double)g_sci[0];
        double hinge = (double)g_scf[0] / (ncs + 1e-6);
        double ctcfl = (ncs < 1.0) ? 0.0 : hinge;
        // compartment
        double cw      = (double)g_sci[32];
        double cb      = 159600.0 * (double)B - cw;   // (L-1)(L-2) masked pairs per batch
        double within  = (double)g_scf[32] / fmax(cw, 1.0);
        double between = ((double)msk - (double)g_scf[32]) / fmax(cb, 1.0);
        double ratio   = within / (fabs(between) + 1e-6);
        double compl_  = fmax(1.5 - ratio, 0.0);

        out[0] = (float)dist;
        out[1] = (float)ctcfl;
        out[2] = (float)compl_;
        out[3] = (float)(dist + 0.5 * ctcfl + 0.5 * compl_);
    }

    // ---------- reset state for next replay ----------
    __syncthreads();
    g_bins[t0 * 32] = 0.f;
    if (hb1) g_bins[t1 * 32] = 0.f;
    if (tid < 2) { g_scf[tid * 32] = 0.f; g_sci[tid * 32] = 0; }
    if (tid == 0) g_done = 0u;
}

// ---------------- launch ----------------
extern "C" void kernel_launch(void* const* d_in, const int* in_sizes, int n_in,
                              void* d_out, int out_size) {
    const float* cm     = (const float*)d_in[0];   // (B, L, L) f32
    const float* logits = (const float*)d_in[1];   // (B, L, 2) f32
    const int*   ctcf   = (const int*)d_in[2];     // (B, L)    i32
    float*       out    = (float*)d_out;           // 4 f32

    prep_kernel<<<L + B, 512>>>(ctcf, logits);
    dim3 grid(NCHUNK, L);
    main_kernel<<<grid, 256>>>(cm, out);
}

// round 15
// speedup vs baseline: 2.0285x; 1.0402x over previous
#include <cuda_runtime.h>
#include <math.h>
#include <stdint.h>

#define L   401
#define B   256
#define LL  (L * L)
#define NCHUNK 4                 // batch chunks in main grid
#define BCHUNK (B / NCHUNK)      // 64 batches per main block (2 bit-plane words)
#define PW  (3 * L)              // words per batch-word slab: [plane][j]
#define NBLK (NCHUNK * L)        // 1604 main blocks

// ---------------- device globals ----------------
__device__ float    g_bins[L * 32];        // one bin per 128B line: bin d at [d*32]
__device__ float    g_scf[2 * 32];         // [0]=ctcf_num, [32]=within_num
__device__ int      g_sci[2 * 32];         // [0]=nc_sum,   [32]=cnt_within (exact ints)
__device__ uint32_t g_planes[8 * PW];      // [batch_word][plane f/r/c][j], bit = b%32
__device__ unsigned int g_done;

// ---------------- kernel 1: merged prep (planes + analytic counts) ----------------
__global__ __launch_bounds__(512) void prep_kernel(const int* __restrict__ ctcf,
                                                   const float* __restrict__ logits) {
    const int blk = blockIdx.x;
    const int t   = threadIdx.x;

    if (blk < L) {
        if (t < B) {
            const int p = blk, b = t;
            int o = ctcf[b * L + p];
            float l0 = logits[(b * L + p) * 2 + 0];
            float l1 = logits[(b * L + p) * 2 + 1];
            uint32_t bf = __ballot_sync(0xffffffffu, o == 1);
            uint32_t br = __ballot_sync(0xffffffffu, o == -1);
            uint32_t bc = __ballot_sync(0xffffffffu, l1 > l0);
            if ((b & 31) == 0) {
                int w = b >> 5;
                g_planes[w * PW + 0 * L + p] = bf;
                g_planes[w * PW + 1 * L + p] = br;
                g_planes[w * PW + 2 * L + p] = bc;
            }
        }
    } else {
        const int b = blk - L;
        const int p = t;
        __shared__ int cnt[5];                 // A, F, R, n1, adjEq
        __shared__ unsigned char compsh[L];
        if (p < 5) cnt[p] = 0;
        __syncthreads();

        int a = 0, f = 0, r = 0, c = 0;
        if (p < L) {
            int o = ctcf[b * L + p];
            a = (o != 0);
            f = (o == 1);
            r = (o == -1);
            float l0 = logits[(b * L + p) * 2 + 0];
            float l1 = logits[(b * L + p) * 2 + 1];
            c = (l1 > l0);                     // argmax, ties -> 0
            compsh[p] = (unsigned char)c;
        }
        __syncthreads();

        int adj = 0;
        if (p < L - 1) adj = (compsh[p] == compsh[p + 1]);

        atomicAdd(&cnt[0], a);
        atomicAdd(&cnt[1], f);
        atomicAdd(&cnt[2], r);
        atomicAdd(&cnt[3], c);
        atomicAdd(&cnt[4], adj);
        __syncthreads();

        if (p == 0) {
            int A = cnt[0], F = cnt[1], R = cnt[2], n1 = cnt[3];
            int n0 = L - n1;
            int nc = A * A - F * R;                            // non_conv count (exact)
            int cw = n0 * n0 + n1 * n1 - L - 2 * cnt[4];       // same & d>=2 (exact)
            atomicAdd(&g_sci[0],  nc);
            atomicAdd(&g_sci[32], cw);
        }
    }
}

// ---------------- kernel 2: TMA-bulk-prefetched streaming + last-block finalize ----
// block = (batch chunk, row i); thread tid owns j0 = tid and (tid<145) j1 = tid+256.
// Each of the block's 64 row-slices is bulk-prefetched into L2 via the TMA engine
// (no smem dest, no mbarrier — zero correctness surface). Demand LDGs then ride
// L2-hit latency (~250cyc) instead of DRAM (~577cyc), lifting the per-SM
// outstanding-line throughput cap.
__global__ __launch_bounds__(256) void main_kernel(const float* __restrict__ cm,
                                                   float* __restrict__ out) {
    const int i   = blockIdx.y;
    const int tid = threadIdx.x;
    const int w0  = blockIdx.x * 2;        // first batch-word of this chunk

    __shared__ uint32_t sh[2 * PW];        // 9.6 KB: the 2 batch-words this block needs

    // ---- bulk L2 prefetch of this block's 64 row-slices (TMA engine) ----
    if (tid < BCHUNK) {
        const char* cmb = (const char*)cm;
        const size_t total = (size_t)B * LL * 4u;
        const size_t e = ((size_t)(blockIdx.x * BCHUNK + tid) * LL + (size_t)i * L) * 4u;
        const char* src = cmb + e;
        const uint32_t fr = (uint32_t)((uintptr_t)src & 15u);
        const char* wnd = src - fr;
        uint32_t sz = 1616u;                       // covers 1604B row for fr <= 12
        if (e - fr + 1616u > total) sz = 1600u;    // clamp at tensor end (last row only)
        asm volatile("cp.async.bulk.prefetch.L2.global [%0], %1;"
                     :: "l"(wnd), "r"(sz) : "memory");
    }

    for (int idx = tid; idx < 2 * PW; idx += 256)
        sh[idx] = g_planes[w0 * PW + idx];
    __syncthreads();

    const int  j0   = tid;
    const int  j1   = tid + 256;
    const bool has1 = (j1 < L);
    const int  d0   = abs(i - j0);
    const int  d1   = has1 ? abs(i - j1) : 0;

    float s0 = 0.f, s1 = 0.f, ct = 0.f, wn = 0.f;
    const float* base = cm + (size_t)(blockIdx.x * BCHUNK) * LL + (size_t)i * L + j0;

#pragma unroll
    for (int h = 0; h < 2; ++h) {
        const uint32_t* s = sh + h * PW;
        const uint32_t fi = s[i], ri = s[L + i], ci = s[2 * L + i];
        const uint32_t ai = fi | ri;

        const uint32_t fj = s[j0], rj = s[L + j0], cj = s[2 * L + j0];
        const uint32_t t10 = ai & (fj | rj) & ~(fi & rj);    // ctcf pair & not convergent
        const uint32_t t20 = (d0 >= 2) ? ~(ci ^ cj) : 0u;    // same compartment & d>=2

        uint32_t t11 = 0u, t21 = 0u;
        if (has1) {
            uint32_t fk = s[j1], rk = s[L + j1], ck = s[2 * L + j1];
            t11 = ai & (fk | rk) & ~(fi & rk);
            t21 = (d1 >= 2) ? ~(ci ^ ck) : 0u;
        }

        const float* pb = base + h * 32 * LL;

#pragma unroll
        for (int c4 = 0; c4 < 4; ++c4) {
            // batch-issue 8 (+8) loads before any consumption
            float v0[8], v1[8];
#pragma unroll
            for (int k = 0; k < 8; ++k)
                v0[k] = __ldcs(pb + (c4 * 8 + k) * LL);
            if (has1) {
#pragma unroll
                for (int k = 0; k < 8; ++k)
                    v1[k] = __ldcs(pb + (c4 * 8 + k) * LL + 256);
            }

#pragma unroll
            for (int k = 0; k < 8; ++k) {
                const int kk = c4 * 8 + k;
                float v = v0[k];
                s0 += v;
                if ((t10 >> kk) & 1u) ct += fmaxf(v, 0.f);
                if ((t20 >> kk) & 1u) wn += v;
            }
            if (has1) {
#pragma unroll
                for (int k = 0; k < 8; ++k) {
                    const int kk = c4 * 8 + k;
                    float u = v1[k];
                    s1 += u;
                    if ((t11 >> kk) & 1u) ct += fmaxf(u, 0.f);
                    if ((t21 >> kk) & 1u) wn += u;
                }
            }
        }
    }

    // one float atomic per thread-slot; bins padded to 1 per 128B line (401 LTS slices)
    atomicAdd(&g_bins[d0 * 32], s0);
    if (has1) atomicAdd(&g_bins[d1 * 32], s1);

    // block-reduce scalars -> one float atomic each
    for (int o = 16; o; o >>= 1) {
        ct += __shfl_down_sync(0xffffffffu, ct, o);
        wn += __shfl_down_sync(0xffffffffu, wn, o);
    }
    __shared__ float red[2][8];
    int wid = tid >> 5, lane = tid & 31;
    if (lane == 0) { red[0][wid] = ct; red[1][wid] = wn; }
    __syncthreads();
    if (tid == 0) {
        float c = 0.f, ww = 0.f;
#pragma unroll
        for (int k = 0; k < 8; ++k) { c += red[0][k]; ww += red[1][k]; }
        atomicAdd(&g_scf[0],  c);
        atomicAdd(&g_scf[32], ww);
    }

    // ---------- last-block finalize ----------
    __threadfence();
    __shared__ unsigned int rank_sh;
    if (tid == 0) rank_sh = atomicAdd(&g_done, 1u);
    __syncthreads();
    if (rank_sh != NBLK - 1) return;
    __threadfence();

    const int t0 = tid, t1 = tid + 256;
    const bool hb1 = (t1 < L);

    float w0_ = 0.f, ld0 = 0.f, lp0 = 0.f;
    float w1_ = 0.f, ld1 = 0.f, lp1 = 0.f;
    float v4[4] = {0.f, 0.f, 0.f, 0.f};    // n, sum(w*ld), sum(w*lp), masked-sum
    {
        float binv = g_bins[t0 * 32];
        float cntp = (t0 == 0) ? (float)L : 2.0f * (float)(L - t0);
        float mc = binv / (cntp * (float)B);
        bool valid = (t0 >= 2) && isfinite(mc) && (mc > 0.0f);
        w0_ = valid ? 1.f : 0.f;
        ld0 = logf(fmaxf((float)t0, 1.0f));
        lp0 = logf((valid ? mc : 1.0f) + 1e-6f);
        v4[0] += w0_; v4[1] += w0_ * ld0; v4[2] += w0_ * lp0;
        if (t0 >= 2) v4[3] += binv;
    }
    if (hb1) {
        float binv = g_bins[t1 * 32];
        float cntp = 2.0f * (float)(L - t1);
        float mc = binv / (cntp * (float)B);
        bool valid = isfinite(mc) && (mc > 0.0f);   // t1 >= 256 >= 2 always
        w1_ = valid ? 1.f : 0.f;
        ld1 = logf((float)t1);
        lp1 = logf((valid ? mc : 1.0f) + 1e-6f);
        v4[0] += w1_; v4[1] += w1_ * ld1; v4[2] += w1_ * lp1;
        v4[3] += binv;
    }

    __shared__ float sc4[4][8];
    __shared__ float tot[4];
#pragma unroll
    for (int o = 16; o; o >>= 1)
#pragma unroll
        for (int q = 0; q < 4; ++q) v4[q] += __shfl_down_sync(0xffffffffu, v4[q], o);
    if (lane == 0) { sc4[0][wid] = v4[0]; sc4[1][wid] = v4[1]; sc4[2][wid] = v4[2]; sc4[3][wid] = v4[3]; }
    __syncthreads();
    if (tid < 4) {
        float sAcc = 0.f;
#pragma unroll
        for (int k = 0; k < 8; ++k) sAcc += sc4[tid][k];
        tot[tid] = sAcc;
    }
    __syncthreads();

    float n  = tot[0];
    float ns = fmaxf(n, 1.0f);
    float xm = tot[1] / ns, ym = tot[2] / ns;
    float msk = tot[3];

    float v2[2];
    v2[0] = w0_ * (ld0 - xm) * (lp0 - ym) + w1_ * (ld1 - xm) * (lp1 - ym);
    v2[1] = w0_ * (ld0 - xm) * (ld0 - xm) + w1_ * (ld1 - xm) * (ld1 - xm);
#pragma unroll
    for (int o = 16; o; o >>= 1)
#pragma unroll
        for (int q = 0; q < 2; ++q) v2[q] += __shfl_down_sync(0xffffffffu, v2[q], o);
    if (lane == 0) { sc4[0][wid] = v2[0]; sc4[1][wid] = v2[1]; }
    __syncthreads();
    if (tid == 0) {
        float num = 0.f, den = 0.f;
#pragma unroll
        for (int k = 0; k < 8; ++k) { num += sc4[0][k]; den += sc4[1][k]; }

        // distance decay
        double slope = (double)num / ((double)den + 1e-8);
        double dist  = (n >= 5.0f) ? (slope + 0.85) * (slope + 0.85) : 0.0;
        // ctcf
        double ncs   = (double)g_sci[0];
        double hinge = (double)g_scf[0] / (ncs + 1e-6);
        double ctcfl = (ncs < 1.0) ? 0.0 : hinge;
        // compartment
        double cw      = (double)g_sci[32];
        double cb      = 159600.0 * (double)B - cw;   // (L-1)(L-2) masked pairs per batch
        double within  = (double)g_scf[32] / fmax(cw, 1.0);
        double between = ((double)msk - (double)g_scf[32]) / fmax(cb, 1.0);
        double ratio   = within / (fabs(between) + 1e-6);
        double compl_  = fmax(1.5 - ratio, 0.0);

        out[0] = (float)dist;
        out[1] = (float)ctcfl;
        out[2] = (float)compl_;
        out[3] = (float)(dist + 0.5 * ctcfl + 0.5 * compl_);
    }

    // ---------- reset state for next replay ----------
    __syncthreads();
    g_bins[t0 * 32] = 0.f;
    if (hb1) g_bins[t1 * 32] = 0.f;
    if (tid < 2) { g_scf[tid * 32] = 0.f; g_sci[tid * 32] = 0; }
    if (tid == 0) g_done = 0u;
}

// ---------------- launch ----------------
extern "C" void kernel_launch(void* const* d_in, const int* in_sizes, int n_in,
                              void* d_out, int out_size) {
    const float* cm     = (const float*)d_in[0];   // (B, L, L) f32
    const float* logits = (const float*)d_in[1];   // (B, L, 2) f32
    const int*   ctcf   = (const int*)d_in[2];     // (B, L)    i32
    float*       out    = (float*)d_out;           // 4 f32

    prep_kernel<<<L + B, 512>>>(ctcf, logits);
    dim3 grid(NCHUNK, L);
    main_kernel<<<grid, 256>>>(cm, out);
}